// round 6
// baseline (speedup 1.0000x reference)
#include <cuda_runtime.h>
#include <cuda_bf16.h>

#define MAX_ROWS 8192
#define NSLOTS 8       // SMEM ring slots per thread (16B each)
#define DEPTH  3       // commit-groups (pairs of chunks) in flight

__device__ double g_row_loss[MAX_ROWS];
__device__ unsigned int g_done = 0;   // self-resets each run -> graph-replay safe

__device__ __forceinline__ float ex2(float x) {
    float y;
    asm("ex2.approx.f32 %0, %1;" : "=f"(y) : "f"(x));
    return y;
}

// One 128-thread block per row -> 2048 blocks, ~14 resident blocks/SM:
// the ENTIRE grid fits in ONE wave (R5 lesson: 1.73 waves left DRAM at 60%
// while per-warp MLP was already 7x past the BW*latency product).
// cp.async ring, 2 chunks per commit group, depth 3 (3KB in flight per warp).
__global__ void __launch_bounds__(128, 14) cosarc_fused_kernel(
    const float* __restrict__ preds,
    const int* __restrict__ labels,     // int32 (JAX x64 disabled)
    float* __restrict__ out,
    int V, int B)
{
    __shared__ float4 buf[NSLOTS][128];

    const int tid = threadIdx.x;
    const int wid = tid >> 5;           // 4 warps
    const int lid = tid & 31;
    const int row = blockIdx.x;
    const float* rp = preds + (size_t)row * (size_t)V;
    const float4* p4 = reinterpret_cast<const float4*>(rp);
    const int n4 = V >> 2;

    // Per-warp contiguous float4 range (4 warps/block).
    const int start = (int)(((long long)n4 * wid) >> 2);
    const int end   = (int)(((long long)n4 * (wid + 1)) >> 2);
    const int chunks = (end - start + 31) >> 5;       // 32-lane chunks
    const int npairs = (chunks + 1) >> 1;

    const float C = 30.0f * 1.4426950408889634f;      // exp(30x) = exp2(C*x)
    float s0 = 0.f, s1 = 0.f;

    // Prologue: issue DEPTH pairs (2 chunks per commit group).
    #pragma unroll
    for (int p = 0; p < DEPTH; p++) {
        #pragma unroll
        for (int h = 0; h < 2; h++) {
            int c = 2 * p + h;
            int g = start + c * 32 + lid;
            if (c < chunks && g < end) {
                unsigned int dst = (unsigned int)__cvta_generic_to_shared(&buf[c & (NSLOTS - 1)][tid]);
                asm volatile("cp.async.cg.shared.global [%0], [%1], 16;"
                             :: "r"(dst), "l"(p4 + g) : "memory");
            }
        }
        asm volatile("cp.async.commit_group;" ::: "memory");
    }

    for (int p = 0; p < npairs; p++) {
        asm volatile("cp.async.wait_group %0;" :: "n"(DEPTH - 1) : "memory");

        // Consume pair p (chunks 2p, 2p+1).
        #pragma unroll
        for (int h = 0; h < 2; h++) {
            int c = 2 * p + h;
            int g = start + c * 32 + lid;
            if (g < end) {
                float4 v = buf[c & (NSLOTS - 1)][tid];
                s0 += ex2(v.x * C) + ex2(v.y * C);
                s1 += ex2(v.z * C) + ex2(v.w * C);
            }
        }

        // Issue pair p+DEPTH. Slot reuse distance = NSLOTS chunks = 4 pairs,
        // pending <= DEPTH pairs -> previous tenant already consumed (no WAR).
        #pragma unroll
        for (int h = 0; h < 2; h++) {
            int c = 2 * (p + DEPTH) + h;
            int g = start + c * 32 + lid;
            if (c < chunks && g < end) {
                unsigned int dst = (unsigned int)__cvta_generic_to_shared(&buf[c & (NSLOTS - 1)][tid]);
                asm volatile("cp.async.cg.shared.global [%0], [%1], 16;"
                             :: "r"(dst), "l"(p4 + g) : "memory");
            }
        }
        asm volatile("cp.async.commit_group;" ::: "memory");
    }
    // Scalar tail (V % 4 != 0) — not hit for V=32000.
    for (int j = (n4 << 2) + tid; j < V; j += 128)
        s0 += ex2(rp[j] * C);

    float sum = s0 + s1;

    #pragma unroll
    for (int o = 16; o > 0; o >>= 1)
        sum += __shfl_xor_sync(0xffffffffu, sum, o);

    __shared__ float warpsum[4];
    if (lid == 0) warpsum[wid] = sum;
    __syncthreads();

    if (tid == 0) {
        float tot = (warpsum[0] + warpsum[1]) + (warpsum[2] + warpsum[3]);

        int lab = labels[row];
        if (lab < 0) lab = 0;
        if (lab >= V) lab = V - 1;
        const float target = rp[lab];

        double sum_others = (double)tot - (double)ex2(target * C);

        const double EPS = 1e-12;
        const double PI  = 3.14159265358979323846;
        double t = (double)target;
        t = fmin(fmax(t, -1.0 + EPS), 1.0 - EPS);
        double theta = acos(t);
        theta = fmin(fmax(theta, EPS), PI - EPS);
        double numerator = 30.0 * (cos(theta + 0.5) - 0.35);
        double denominator = exp(numerator) + sum_others;
        g_row_loss[row] = numerator - log(denominator);
    }

    // ---- last-block-done final reduction (deterministic fixed-order sum) ----
    __threadfence();
    __shared__ bool is_last;
    if (tid == 0)
        is_last = (atomicAdd(&g_done, 1u) == (unsigned)(gridDim.x - 1));
    __syncthreads();

    if (is_last) {
        double d = 0.0;
        for (int j = tid; j < B; j += 128)
            d += g_row_loss[j];

        #pragma unroll
        for (int o = 16; o > 0; o >>= 1)
            d += __shfl_xor_sync(0xffffffffu, d, o);

        __shared__ double dwarp[4];
        if (lid == 0) dwarp[wid] = d;
        __syncthreads();

        if (tid == 0) {
            double tot = (dwarp[0] + dwarp[1]) + (dwarp[2] + dwarp[3]);
            out[0] = (float)(-tot / (double)B);
            g_done = 0;   // reset for next graph replay
        }
    }
}

extern "C" void kernel_launch(void* const* d_in, const int* in_sizes, int n_in,
                              void* d_out, int out_size)
{
    const float* preds  = (const float*)d_in[0];
    const int*   labels = (const int*)d_in[1];

    const int B = in_sizes[1];                 // 2048
    const int V = in_sizes[0] / B;             // 32000

    cosarc_fused_kernel<<<B, 128>>>(preds, labels, (float*)d_out, V, B);
}